// round 11
// baseline (speedup 1.0000x reference)
#include <cuda_runtime.h>
#include <cuda_bf16.h>
#include <cstdint>
#include <math.h>

// ---------------- problem constants ----------------
#define TSTEPS 512
#define BATCH  64
#define DIN    1024
#define DHID   1024

// ---------------- persistent-loop config ----------------
#define NCTA 128                 // persistent CTAs; CTA owns 8 hidden dims = 32 gemm cols
#define NTHR 256                 // 8 warps: mgroup = wid&1, kslice = wid>>1
#define NCHL 16                  // recurrent K chunks (1024/64)

// loop SMEM layout (bytes)
#define ZSTG    16384            // per stage: zhi 8K | zlo 8K
#define NSTG    3
#define WOFF    (NSTG * ZSTG)                // 49152 : W_h resident 128KB
#define PX_OFF  (WOFF + 131072)              // 180224: px 64x33 floats = 8448
#define PP_STRIDE 34
#define PP_SLICE  (BATCH * PP_STRIDE)        // 2176 floats per k-slice
#define PP_OFF  (PX_OFF + 8448)              // 188672: pre_part [4][2176] floats = 34816
#define C_OFF   (PP_OFF + 34816)             // 223488: c state 512 floats
#define BIAS_OFF (C_OFF + 2048)              // 225536: 32 floats
#define LEN_OFF (BIAS_OFF + 128)             // 225664: 64 ints
#define BASE_OFF (LEN_OFF + 256)             // 225920: base_cnt[16] + base_done
#define SMEM_LOOP (BASE_OFF + 17 * 8)        // 226056

// precompute GEMM smem: 2 stages x (A 4x16KB + B 32KB)
#define PSTG_BYTES 98304
#define SMEM_PRE   (2 * PSTG_BYTES)

#define PX_ROWB 2112             // floats per (t,cta) px block: 64 rows x 33

// ---------------- device-global scratch (static; no cudaMalloc) ----------------
__device__ __align__(16) unsigned char g_zx[(size_t)TSTEPS*16*16384];  // x tiles [t*16+ch][hi8K|lo8K]
__device__ __align__(16) unsigned char g_zh[(size_t)3*16*16384];       // h tiles [slot*16+chl][hi8K|lo8K], TRIPLE buffered
__device__ __align__(16) unsigned char g_Wxt[(size_t)32*16*32768];     // Wx tiles [ng*16+ch][hi16K|lo16K]
__device__ __align__(16) unsigned char g_Wht[(size_t)NCTA*NCHL*8192];  // Wh tiles [cta*16+ch][hi4K|lo4K]
__device__ float g_px[(size_t)TSTEPS*NCTA*PX_ROWB];                    // x-projection [t][cta][b*33+c]
__device__ unsigned long long g_bar;           // init grid-barrier ticket (monotonic)
__device__ unsigned long long g_cnt[NCHL];     // per-h-chunk producer arrivals (monotonic)
__device__ unsigned long long g_done;          // per-CTA chunk-loop-complete arrivals (monotonic)

// ---------------- helpers ----------------
__host__ __device__ __forceinline__ uint32_t swz128(uint32_t x) { return x ^ ((x >> 3) & 0x70); }

__device__ __forceinline__ uint32_t smem_u32(const void* p) {
    uint32_t a;
    asm("{ .reg .u64 t; cvta.to.shared.u64 t, %1; cvt.u32.u64 %0, t; }" : "=r"(a) : "l"(p));
    return a;
}
union U4 { unsigned short s[8]; uint4 v; };
__device__ __forceinline__ void bf16split(float v, unsigned short& hi, unsigned short& lo) {
    __nv_bfloat16 h = __float2bfloat16_rn(v);
    float r = v - __bfloat162float(h);
    __nv_bfloat16 l = __float2bfloat16_rn(r);
    hi = reinterpret_cast<unsigned short&>(h);
    lo = reinterpret_cast<unsigned short&>(l);
}
__device__ __forceinline__ unsigned short bf16hi(float v) {
    __nv_bfloat16 h = __float2bfloat16_rn(v);
    return reinterpret_cast<unsigned short&>(h);
}
__device__ __forceinline__ void cp16(uint32_t saddr, const void* gaddr) {
    asm volatile("cp.async.cg.shared.global [%0], [%1], 16;" :: "r"(saddr), "l"(gaddr));
}
__device__ __forceinline__ void cp_commit() { asm volatile("cp.async.commit_group;"); }
template <int N> __device__ __forceinline__ void cp_wait() {
    asm volatile("cp.async.wait_group %0;" :: "n"(N));
}
__device__ __forceinline__ void ldsm4(uint32_t& r0, uint32_t& r1, uint32_t& r2, uint32_t& r3, uint32_t a) {
    asm volatile("ldmatrix.sync.aligned.m8n8.x4.shared.b16 {%0,%1,%2,%3}, [%4];"
                 : "=r"(r0), "=r"(r1), "=r"(r2), "=r"(r3) : "r"(a));
}
__device__ __forceinline__ void ldsm2(uint32_t& r0, uint32_t& r1, uint32_t a) {
    asm volatile("ldmatrix.sync.aligned.m8n8.x2.shared.b16 {%0,%1}, [%2];"
                 : "=r"(r0), "=r"(r1) : "r"(a));
}
__device__ __forceinline__ void mma16816(float* d, uint32_t a0, uint32_t a1, uint32_t a2, uint32_t a3,
                                         uint32_t b0, uint32_t b1) {
    asm volatile("mma.sync.aligned.m16n8k16.row.col.f32.bf16.bf16.f32 "
                 "{%0,%1,%2,%3}, {%4,%5,%6,%7}, {%8,%9}, {%0,%1,%2,%3};"
                 : "+f"(d[0]), "+f"(d[1]), "+f"(d[2]), "+f"(d[3])
                 : "r"(a0), "r"(a1), "r"(a2), "r"(a3), "r"(b0), "r"(b1));
}
__device__ __forceinline__ void grid_sync_full() {
    __syncthreads();
    if (threadIdx.x == 0) {
        __threadfence();
        unsigned long long t = atomicAdd(&g_bar, 1ULL);
        unsigned long long target = (t / NCTA + 1ULL) * NCTA;
        while (*(volatile unsigned long long*)&g_bar < target) __nanosleep(64);
        __threadfence();
    }
    __syncthreads();
}
__device__ __forceinline__ float sigmoidf_(float x) { return 1.0f / (1.0f + expf(-x)); }

// ============ init 1: x -> pre-swizzled bf16 hi/lo SW128 tiles ============
__global__ void cvt_x_kernel(const float* __restrict__ batch) {
    int bid = blockIdx.x;                 // t*16 + ch
    int tid = threadIdx.x;                // 128
    int b = tid >> 1, half = tid & 1;
    int t = bid >> 4, ch = bid & 15;
    const float* src = batch + ((size_t)t * BATCH + b) * DIN + ch * 64 + half * 32;
    unsigned char* dhi = g_zx + (size_t)bid * 16384;
    unsigned char* dlo = dhi + 8192;
    #pragma unroll
    for (int q = 0; q < 4; ++q) {
        float v[8];
        *(float4*)&v[0] = *(const float4*)(src + q * 8);
        *(float4*)&v[4] = *(const float4*)(src + q * 8 + 4);
        U4 hi, lo;
        #pragma unroll
        for (int j = 0; j < 8; ++j) bf16split(v[j], hi.s[j], lo.s[j]);
        uint32_t off = swz128((uint32_t)b * 128 + (uint32_t)(half * 4 + q) * 16);
        *(uint4*)(dhi + off) = hi.v;
        *(uint4*)(dlo + off) = lo.v;
    }
}

// ============ init 2 (FUSED): W_x tiles (bid<512) + W_h tiles (bid>=512) ============
__global__ void cvt_w_kernel(const float* __restrict__ Wi, const float* __restrict__ Wf,
                             const float* __restrict__ Wc, const float* __restrict__ Wo) {
    __shared__ float sraw[4][64][8];
    const float* Wsrc[4] = {Wi, Wf, Wc, Wo};
    int tid = threadIdx.x;                // 256
    if (blockIdx.x < 512) {
        int bid = blockIdx.x;             // ng*16 + ch
        int ng = bid >> 4, ch = bid & 15;
        int j = tid >> 1, khalf = tid & 1;
        int q = j >> 5, c = j & 31, gate = c >> 3;
        int wcol = (4 * ng + q) * 8 + (c & 7);
        const float* src = Wsrc[gate] + (size_t)(ch * 64 + khalf * 32) * DHID + wcol;
        unsigned char* dst = g_Wxt + (size_t)bid * 32768;
        #pragma unroll
        for (int qq = 0; qq < 4; ++qq) {
            U4 hi, lo;
            #pragma unroll
            for (int kk = 0; kk < 8; ++kk)
                bf16split(src[(size_t)(qq * 8 + kk) * DHID], hi.s[kk], lo.s[kk]);
            uint32_t off = swz128((uint32_t)j * 128 + (uint32_t)(khalf * 4 + qq) * 16);
            *(uint4*)(dst + off) = hi.v;
            *(uint4*)(dst + 16384 + off) = lo.v;
        }
    } else {
        int bid = blockIdx.x - 512;       // cta*16 + ch
        int cta = bid >> 4, ch = bid & 15;
        {
            int g = tid >> 6, kk = tid & 63;
            const float* s = Wsrc[g] + (size_t)(1024 + ch * 64 + kk) * DHID + cta * 8;
            float4 a = *(const float4*)s, b = *(const float4*)(s + 4);
            sraw[g][kk][0] = a.x; sraw[g][kk][1] = a.y; sraw[g][kk][2] = a.z; sraw[g][kk][3] = a.w;
            sraw[g][kk][4] = b.x; sraw[g][kk][5] = b.y; sraw[g][kk][6] = b.z; sraw[g][kk][7] = b.w;
        }
        __syncthreads();
        int c = tid >> 3, kkb = tid & 7;
        int g = c >> 3, dd = c & 7;
        U4 hi, lo;
        #pragma unroll
        for (int j = 0; j < 8; ++j) bf16split(sraw[g][kkb * 8 + j][dd], hi.s[j], lo.s[j]);
        unsigned char* dst = g_Wht + (size_t)bid * 8192;
        uint32_t off = swz128((uint32_t)c * 128 + (uint32_t)kkb * 16);
        *(uint4*)(dst + off) = hi.v;
        *(uint4*)(dst + 4096 + off) = lo.v;
    }
}

// ============ precompute GEMM: px[t][cta][b,32c] = x_t @ W_x (3-term split) ============
__global__ __launch_bounds__(256, 1)
void gemm_x_kernel() {
    extern __shared__ __align__(1024) unsigned char sm[];
    const uint32_t smem = smem_u32(sm);
    const int ng = blockIdx.x;
    const int tg = blockIdx.y;
    const int tid = threadIdx.x, wid = tid >> 5, lane = tid & 31;
    const int mt = wid & 3;
    const int nh = wid >> 2;
    const int lane16 = lane & 15;
    const int usel_a = lane >> 4;
    const int usel_b = (lane16 >> 3) & 1;

    int aoff[4][4];
    #pragma unroll
    for (int mi = 0; mi < 4; ++mi) {
        int arow = mi * 16 + lane16, arx = (arow & 7) << 4;
        #pragma unroll
        for (int ks = 0; ks < 4; ++ks)
            aoff[mi][ks] = arow * 128 + ((32 * ks + 16 * usel_a) ^ arx);
    }
    int boff[8][4];
    #pragma unroll
    for (int ni = 0; ni < 8; ++ni) {
        int brow = nh * 64 + ni * 8 + (lane16 & 7), brx = (brow & 7) << 4;
        #pragma unroll
        for (int ks = 0; ks < 4; ++ks)
            boff[ni][ks] = brow * 128 + ((32 * ks + 16 * usel_b) ^ brx);
    }

    float acc[4][8][4];
    #pragma unroll
    for (int mi = 0; mi < 4; ++mi)
        #pragma unroll
        for (int ni = 0; ni < 8; ++ni)
            #pragma unroll
            for (int q = 0; q < 4; ++q) acc[mi][ni][q] = 0.0f;

    auto issueP = [&](int ch) {
        uint32_t sb = smem + (uint32_t)(ch & 1) * PSTG_BYTES;
        #pragma unroll
        for (int i = 0; i < 16; ++i) {
            int j = tid + i * 256;
            int tt = j >> 10, off = j & 1023;
            cp16(sb + tt * 16384 + off * 16,
                 g_zx + ((size_t)(tg * 4 + tt) * 16 + ch) * 16384 + off * 16);
        }
        #pragma unroll
        for (int i = 0; i < 8; ++i) {
            int j = tid + i * 256;
            cp16(sb + 65536 + j * 16, g_Wxt + ((size_t)(ng * 16 + ch)) * 32768 + j * 16);
        }
        cp_commit();
    };

    issueP(0);
    for (int ch = 0; ch < 16; ++ch) {
        if (ch + 1 < 16) { issueP(ch + 1); cp_wait<1>(); }
        else             cp_wait<0>();
        __syncthreads();
        uint32_t sb  = smem + (uint32_t)(ch & 1) * PSTG_BYTES;
        uint32_t zhi = sb + mt * 16384, zlo = zhi + 8192;
        uint32_t bhi = sb + 65536, blo = bhi + 16384;
        #pragma unroll
        for (int ks = 0; ks < 4; ++ks) {
            uint32_t zh[4][4], zl[4][4], wf[8][2];
            #pragma unroll
            for (int mi = 0; mi < 4; ++mi) ldsm4(zh[mi][0], zh[mi][1], zh[mi][2], zh[mi][3], zhi + aoff[mi][ks]);
            #pragma unroll
            for (int ni = 0; ni < 8; ++ni) ldsm2(wf[ni][0], wf[ni][1], bhi + boff[ni][ks]);
            #pragma unroll
            for (int mi = 0; mi < 4; ++mi)
                #pragma unroll
                for (int ni = 0; ni < 8; ++ni)
                    mma16816(acc[mi][ni], zh[mi][0], zh[mi][1], zh[mi][2], zh[mi][3], wf[ni][0], wf[ni][1]);
            #pragma unroll
            for (int mi = 0; mi < 4; ++mi) ldsm4(zl[mi][0], zl[mi][1], zl[mi][2], zl[mi][3], zlo + aoff[mi][ks]);
            #pragma unroll
            for (int mi = 0; mi < 4; ++mi)
                #pragma unroll
                for (int ni = 0; ni < 8; ++ni)
                    mma16816(acc[mi][ni], zl[mi][0], zl[mi][1], zl[mi][2], zl[mi][3], wf[ni][0], wf[ni][1]);
            #pragma unroll
            for (int ni = 0; ni < 8; ++ni) ldsm2(wf[ni][0], wf[ni][1], blo + boff[ni][ks]);
            #pragma unroll
            for (int mi = 0; mi < 4; ++mi)
                #pragma unroll
                for (int ni = 0; ni < 8; ++ni)
                    mma16816(acc[mi][ni], zh[mi][0], zh[mi][1], zh[mi][2], zh[mi][3], wf[ni][0], wf[ni][1]);
        }
        __syncthreads();
    }

    const int t = tg * 4 + mt;
    #pragma unroll
    for (int mi = 0; mi < 4; ++mi) {
        int r0 = mi * 16 + (lane >> 2);
        #pragma unroll
        for (int ni = 0; ni < 8; ++ni) {
            int j = nh * 64 + ni * 8 + (lane & 3) * 2;
            int q = j >> 5, c = j & 31;
            float* base = g_px + ((size_t)t * NCTA + 4 * ng + q) * PX_ROWB;
            base[r0 * 33 + c]           = acc[mi][ni][0];
            base[r0 * 33 + c + 1]       = acc[mi][ni][1];
            base[(r0 + 8) * 33 + c]     = acc[mi][ni][2];
            base[(r0 + 8) * 33 + c + 1] = acc[mi][ni][3];
        }
    }
}

// ============ h tile writer (init only; epilogue writes per-thread) ============
__device__ __forceinline__ void store_h_tiles(int slot, int cta, int b, const float* h8) {
    int chl = cta >> 3, kkb = cta & 7;
    U4 hi, lo;
    #pragma unroll
    for (int j = 0; j < 8; ++j) bf16split(h8[j], hi.s[j], lo.s[j]);
    uint32_t off = swz128((uint32_t)b * 128 + (uint32_t)kkb * 16);
    unsigned char* base = g_zh + ((size_t)slot * 16 + chl) * 16384;
    *(uint4*)(base + off) = hi.v;
    *(uint4*)(base + 8192 + off) = lo.v;
}

// ============ persistent recurrent kernel: chunk-dataflow sync, tid0-only polls ============
__global__ __launch_bounds__(NTHR, 1)
void lstm_mma_kernel(const int* __restrict__ lengths, const float* __restrict__ c0,
                     const float* __restrict__ bi, const float* __restrict__ bff,
                     const float* __restrict__ bc, const float* __restrict__ bo,
                     float* __restrict__ out) {
    extern __shared__ __align__(1024) unsigned char sm[];
    const uint32_t smem = smem_u32(sm);
    float* px_s   = (float*)(sm + PX_OFF);
    float* pp_s   = (float*)(sm + PP_OFF);     // [4][64*34]
    float* c_s    = (float*)(sm + C_OFF);      // [512]
    float* bias_s = (float*)(sm + BIAS_OFF);   // [32]
    int*   len_s  = (int*)(sm + LEN_OFF);      // [64]
    unsigned long long* base_s = (unsigned long long*)(sm + BASE_OFF);  // [0..15]=cnt, [16]=done

    const int tid = threadIdx.x, wid = tid >> 5, lane = tid & 31;
    const int cta = blockIdx.x;
    const int dbase = cta * 8;

    // baseline snapshot of monotonic counters (stable at kernel entry, pre-barrier)
    if (tid < NCHL) base_s[tid] = g_cnt[tid];
    if (tid == NCHL) base_s[NCHL] = g_done;

    // warp roles: mgroup (rows 32*mg..), kslice (k-residue within chunk)
    const int mg = wid & 1, kslice = wid >> 1;
    const int lane16 = lane & 15;
    const int usel_a = lane >> 4;
    const int usel_b = (lane16 >> 3) & 1;
    int aoff[2], boff[4];
    #pragma unroll
    for (int mi = 0; mi < 2; ++mi) {
        int arow = mg * 32 + mi * 16 + lane16, arx = (arow & 7) << 4;
        aoff[mi] = arow * 128 + ((32 * kslice + 16 * usel_a) ^ arx);
    }
    #pragma unroll
    for (int ni = 0; ni < 4; ++ni) {
        int brow = ni * 8 + (lane16 & 7), brx = (brow & 7) << 4;
        boff[ni] = brow * 128 + ((32 * kslice + 16 * usel_b) ^ brx);
    }

    // ---- init: W_h -> SMEM (resident) ----
    {
        const unsigned char* wsrc = g_Wht + (size_t)cta * (NCHL * 8192);
        for (int i = tid; i < 8192; i += NTHR) cp16(smem + WOFF + i * 16, wsrc + (size_t)i * 16);
        cp_commit(); cp_wait<0>();
    }
    for (int j = tid; j < 512; j += NTHR) c_s[j] = c0[dbase + (j & 7)];
    if (tid < 32) bias_s[tid] = ((tid >> 3) == 0 ? bi : (tid >> 3) == 1 ? bff :
                                 (tid >> 3) == 2 ? bc : bo)[dbase + (tid & 7)];
    if (tid < BATCH) {
        len_s[tid] = lengths[tid];
        float h0[8];
        #pragma unroll
        for (int dd = 0; dd < 8; ++dd) h0[dd] = tanhf(c0[dbase + dd]);
        store_h_tiles(0, cta, tid, h0);     // step-0 reads use slot 0
    }
    grid_sync_full();   // h0 + baselines published before any loop traffic

    const int chl = cta >> 3, kkb = cta & 7;   // epilogue h-tile coords

    // ---- recurrence ----
    for (int t = 0; t < TSTEPS; ++t) {
        const int rslot = t % 3;                 // h slot read this step
        const int wslot = (t + 1) % 3;           // h slot written this step

        // px prefetch (no h dependency) — overlaps the chunk-0/1 producer waits below
        {
            const unsigned char* srcp =
                (const unsigned char*)(g_px + ((size_t)t * NCTA + cta) * PX_ROWB);
            for (int i = tid; i < 528; i += NTHR) cp16(smem + PX_OFF + i * 16, srcp + (size_t)i * 16);
            cp_commit();
        }

        // wait for chunk 0 & 1's 8 producers each (step t-1 epilogues); tid0 only
        if (tid == 0) {
            unsigned long long n0 = base_s[0] + (unsigned long long)(8 * t);
            unsigned long long n1 = base_s[1] + (unsigned long long)(8 * t);
            while (*(volatile unsigned long long*)&g_cnt[0] < n0) __nanosleep(32);
            while (*(volatile unsigned long long*)&g_cnt[1] < n1) __nanosleep(32);
            __threadfence();
        }
        __syncthreads();

        auto issue = [&](int ci) {
            const unsigned char* srcz = g_zh + ((size_t)rslot * 16 + ci) * 16384;
            uint32_t sb = smem + (uint32_t)(ci % NSTG) * ZSTG;
            #pragma unroll
            for (int i = 0; i < 4; ++i) {
                int j = tid + i * NTHR;
                cp16(sb + j * 16, srcz + (size_t)j * 16);
            }
            cp_commit();
        };

        float acc[2][4][4];
        #pragma unroll
        for (int mi = 0; mi < 2; ++mi)
            #pragma unroll
            for (int ni = 0; ni < 4; ++ni)
                #pragma unroll
                for (int q = 0; q < 4; ++q) acc[mi][ni][q] = 0.0f;

        issue(0); issue(1);
        for (int ch = 0; ch < NCHL; ++ch) {
            if (ch < NCHL - 1) cp_wait<1>();   // also drains the px group early on
            else               cp_wait<0>();
            // producer wait for the chunk about to be issued (tid0 only, pre-sync)
            if (tid == 0 && ch + 2 < NCHL) {
                unsigned long long need = base_s[ch + 2] + (unsigned long long)(8 * t);
                while (*(volatile unsigned long long*)&g_cnt[ch + 2] < need) __nanosleep(32);
                __threadfence();
            }
            __syncthreads();
            if (ch + 2 < NCHL) issue(ch + 2);   // post-sync: freed stage is safe to refill

            const uint32_t zb  = smem + (uint32_t)(ch % NSTG) * ZSTG;
            const uint32_t zhi = zb, zlo = zb + 8192;
            const uint32_t whi = smem + WOFF + (uint32_t)ch * 8192, wlo = whi + 4096;

            uint32_t ah[2][4], al[2][4], bh[4][2], bl[4][2];
            #pragma unroll
            for (int mi = 0; mi < 2; ++mi) {
                ldsm4(ah[mi][0], ah[mi][1], ah[mi][2], ah[mi][3], zhi + aoff[mi]);
                ldsm4(al[mi][0], al[mi][1], al[mi][2], al[mi][3], zlo + aoff[mi]);
            }
            #pragma unroll
            for (int ni = 0; ni < 4; ++ni) {
                ldsm2(bh[ni][0], bh[ni][1], whi + boff[ni]);
                ldsm2(bl[ni][0], bl[ni][1], wlo + boff[ni]);
            }
            #pragma unroll
            for (int mi = 0; mi < 2; ++mi)
                #pragma unroll
                for (int ni = 0; ni < 4; ++ni) {
                    mma16816(acc[mi][ni], ah[mi][0], ah[mi][1], ah[mi][2], ah[mi][3], bh[ni][0], bh[ni][1]);
                    mma16816(acc[mi][ni], ah[mi][0], ah[mi][1], ah[mi][2], ah[mi][3], bl[ni][0], bl[ni][1]);
                    mma16816(acc[mi][ni], al[mi][0], al[mi][1], al[mi][2], al[mi][3], bh[ni][0], bh[ni][1]);
                }
        }

        // all global h reads for step t are complete (cp_wait<0> above)
        if (tid == 0) atomicAdd(&g_done, 1ULL);

        // ---- gather K-split partials (warp-private slices; stride 34 keeps float2 aligned) ----
        {
            float* pp = pp_s + kslice * PP_SLICE;
            #pragma unroll
            for (int mi = 0; mi < 2; ++mi) {
                int r0 = mg * 32 + mi * 16 + (lane >> 2);
                #pragma unroll
                for (int ni = 0; ni < 4; ++ni) {
                    int c = ni * 8 + (lane & 3) * 2;
                    *(float2*)&pp[r0 * PP_STRIDE + c]       = make_float2(acc[mi][ni][0], acc[mi][ni][1]);
                    *(float2*)&pp[(r0 + 8) * PP_STRIDE + c] = make_float2(acc[mi][ni][2], acc[mi][ni][3]);
                }
            }
        }
        // WAR guard (2-step slack; essentially never blocks): slot wslot was read at step t-2
        if (tid == 0 && t >= 2) {
            unsigned long long needd = base_s[NCHL] + (unsigned long long)(NCTA * (t - 1));
            while (*(volatile unsigned long long*)&g_done < needd) __nanosleep(32);
        }
        __syncthreads();

        // ---- epilogue: all 256 threads, 2 cells each; out-store deferred past the arrive ----
        const int b = tid >> 2, dd0 = (tid & 3) * 2;
        float h2[2];
        {
            const int myl = len_s[b];
            const int bo34 = b * PP_STRIDE, bo33 = b * 33;
            unsigned short hhw[2], hlw[2];
            #pragma unroll
            for (int r = 0; r < 2; ++r) {
                const int dd = dd0 + r;
                float pre[4];
                #pragma unroll
                for (int g = 0; g < 4; ++g) {
                    const int c = g * 8 + dd;
                    pre[g] = px_s[bo33 + c] + bias_s[c]
                           + pp_s[bo34 + c] + pp_s[PP_SLICE + bo34 + c]
                           + pp_s[2 * PP_SLICE + bo34 + c] + pp_s[3 * PP_SLICE + bo34 + c];
                }
                float ig = sigmoidf_(pre[0]), fg = sigmoidf_(pre[1]);
                float gg = tanhf(pre[2]),     og = sigmoidf_(pre[3]);
                float cn = fg * c_s[b * 8 + dd] + ig * gg;
                float h  = og * tanhf(cn);
                if (t >= myl) h = 0.0f;
                c_s[b * 8 + dd] = cn;
                __nv_bfloat16 hb = __float2bfloat16_rn(h);
                hhw[r] = reinterpret_cast<unsigned short&>(hb);
                hlw[r] = bf16hi(h - __bfloat162float(hb));
                h2[r] = h;
            }
            // h pair -> global tiles (hi/lo) — what the 16 consumers-of-chl wait on
            unsigned char* base = g_zh + ((size_t)wslot * 16 + chl) * 16384;
            uint32_t off = swz128((uint32_t)b * 128 + (uint32_t)kkb * 16) + (uint32_t)dd0 * 2;
            *(uint32_t*)(base + off)        = (uint32_t)hhw[0] | ((uint32_t)hhw[1] << 16);
            *(uint32_t*)(base + 8192 + off) = (uint32_t)hlw[0] | ((uint32_t)hlw[1] << 16);
        }
        __syncthreads();
        if (tid == 0) {        // producer arrive for our h chunk (post-sync fence)
            __threadfence();
            atomicAdd(&g_cnt[chl], 1ULL);
        }
        // output store: off the inter-CTA critical path
        *(float2*)(out + ((size_t)t * BATCH + b) * DHID + dbase + dd0) = make_float2(h2[0], h2[1]);
    }
}

extern "C" void kernel_launch(void* const* d_in, const int* in_sizes, int n_in,
                              void* d_out, int out_size) {
    const float* batch   = (const float*)d_in[0];
    const int*   lengths = (const int*)  d_in[1];
    const float* c0      = (const float*)d_in[2];
    const float* Wi = (const float*)d_in[3];
    const float* bi = (const float*)d_in[4];
    const float* Wf = (const float*)d_in[5];
    const float* bf = (const float*)d_in[6];
    const float* Wc = (const float*)d_in[7];
    const float* bc = (const float*)d_in[8];
    const float* Wo = (const float*)d_in[9];
    const float* bo = (const float*)d_in[10];
    float* out = (float*)d_out;

    cvt_x_kernel<<<TSTEPS * 16, 128>>>(batch);
    cvt_w_kernel<<<512 + NCTA * NCHL, 256>>>(Wi, Wf, Wc, Wo);

    cudaFuncSetAttribute(gemm_x_kernel, cudaFuncAttributeMaxDynamicSharedMemorySize, SMEM_PRE);
    gemm_x_kernel<<<dim3(32, 128), 256, SMEM_PRE>>>();

    cudaFuncSetAttribute(lstm_mma_kernel, cudaFuncAttributeMaxDynamicSharedMemorySize, SMEM_LOOP);
    lstm_mma_kernel<<<NCTA, NTHR, SMEM_LOOP>>>(lengths, c0, bi, bf, bc, bo, out);
}

// round 12
// speedup vs baseline: 1.8696x; 1.8696x over previous
#include <cuda_runtime.h>
#include <cuda_bf16.h>
#include <cstdint>
#include <math.h>

// ---------------- problem constants ----------------
#define TSTEPS 512
#define BATCH  64
#define DIN    1024
#define DHID   1024

// ---------------- persistent-loop config ----------------
#define NCTA 128                 // persistent CTAs; CTA owns 8 hidden dims = 32 gemm cols
#define NTHR 256                 // 8 warps; warp w = k16-residue w of each 128-K chunk
#define NCHB 8                   // big recurrent K chunks (1024/128)

// loop SMEM layout (bytes)
#define ZSTG    32768            // per stage: [Ahi 8K][Bhi 8K][Alo 8K][Blo 8K] (two 64-k tiles)
#define NSTG    3
#define WOFF    (NSTG * ZSTG)                // 98304 : W_h resident 128KB (16 x (hi4K|lo4K))
#define PP_STRIDE 34
#define PP_SLICE  (BATCH * PP_STRIDE)        // 2176 floats per k-slice
// pp [8][2176] floats = 69632 B — ALIASED onto the stage region (post-loop, sync-guarded)
#define C_OFF   (WOFF + 131072)              // 229376: c state 512 floats
#define BIAS_OFF (C_OFF + 2048)              // 231424: 32 floats
#define LEN_OFF (BIAS_OFF + 128)             // 231552: 64 ints
#define TGT_OFF (LEN_OFF + 256)              // 231808
#define SMEM_LOOP (TGT_OFF + 16)             // 231824 (< 232448 max)

// precompute GEMM smem: 2 stages x (A 4x16KB + B 32KB)
#define PSTG_BYTES 98304
#define SMEM_PRE   (2 * PSTG_BYTES)

#define PX_ROWB 2112             // floats per (t,cta) px block: 64 rows x 33

// ---------------- device-global scratch (static; no cudaMalloc) ----------------
__device__ __align__(16) unsigned char g_zx[(size_t)TSTEPS*16*16384];  // x tiles [t*16+ch][hi8K|lo8K]
__device__ __align__(16) unsigned char g_zh[(size_t)2*16*16384];       // h tiles [buf*16+chl][hi8K|lo8K]
__device__ __align__(16) unsigned char g_Wxt[(size_t)32*16*32768];     // Wx tiles [ng*16+ch][hi16K|lo16K]
__device__ __align__(16) unsigned char g_Wht[(size_t)NCTA*16*8192];    // Wh tiles [cta*16+ch][hi4K|lo4K]
__device__ float g_px[(size_t)TSTEPS*NCTA*PX_ROWB];                    // x-projection [t][cta][b*33+c]
__device__ unsigned long long g_bar;   // monotonic grid-barrier ticket

// ---------------- helpers ----------------
__host__ __device__ __forceinline__ uint32_t swz128(uint32_t x) { return x ^ ((x >> 3) & 0x70); }

__device__ __forceinline__ uint32_t smem_u32(const void* p) {
    uint32_t a;
    asm("{ .reg .u64 t; cvta.to.shared.u64 t, %1; cvt.u32.u64 %0, t; }" : "=r"(a) : "l"(p));
    return a;
}
union U4 { unsigned short s[8]; uint4 v; };
__device__ __forceinline__ void bf16split(float v, unsigned short& hi, unsigned short& lo) {
    __nv_bfloat16 h = __float2bfloat16_rn(v);
    float r = v - __bfloat162float(h);
    __nv_bfloat16 l = __float2bfloat16_rn(r);
    hi = reinterpret_cast<unsigned short&>(h);
    lo = reinterpret_cast<unsigned short&>(l);
}
__device__ __forceinline__ unsigned short bf16hi(float v) {
    __nv_bfloat16 h = __float2bfloat16_rn(v);
    return reinterpret_cast<unsigned short&>(h);
}
__device__ __forceinline__ void cp16(uint32_t saddr, const void* gaddr) {
    asm volatile("cp.async.cg.shared.global [%0], [%1], 16;" :: "r"(saddr), "l"(gaddr));
}
__device__ __forceinline__ void cp_commit() { asm volatile("cp.async.commit_group;"); }
template <int N> __device__ __forceinline__ void cp_wait() {
    asm volatile("cp.async.wait_group %0;" :: "n"(N));
}
__device__ __forceinline__ void ldsm4(uint32_t& r0, uint32_t& r1, uint32_t& r2, uint32_t& r3, uint32_t a) {
    asm volatile("ldmatrix.sync.aligned.m8n8.x4.shared.b16 {%0,%1,%2,%3}, [%4];"
                 : "=r"(r0), "=r"(r1), "=r"(r2), "=r"(r3) : "r"(a));
}
__device__ __forceinline__ void ldsm2(uint32_t& r0, uint32_t& r1, uint32_t a) {
    asm volatile("ldmatrix.sync.aligned.m8n8.x2.shared.b16 {%0,%1}, [%2];"
                 : "=r"(r0), "=r"(r1) : "r"(a));
}
__device__ __forceinline__ void mma16816(float* d, uint32_t a0, uint32_t a1, uint32_t a2, uint32_t a3,
                                         uint32_t b0, uint32_t b1) {
    asm volatile("mma.sync.aligned.m16n8k16.row.col.f32.bf16.bf16.f32 "
                 "{%0,%1,%2,%3}, {%4,%5,%6,%7}, {%8,%9}, {%0,%1,%2,%3};"
                 : "+f"(d[0]), "+f"(d[1]), "+f"(d[2]), "+f"(d[3])
                 : "r"(a0), "r"(a1), "r"(a2), "r"(a3), "r"(b0), "r"(b1));
}
__device__ __forceinline__ void grid_sync_full() {
    __syncthreads();
    if (threadIdx.x == 0) {
        __threadfence();
        unsigned long long t = atomicAdd(&g_bar, 1ULL);
        unsigned long long target = (t / NCTA + 1ULL) * NCTA;
        while (*(volatile unsigned long long*)&g_bar < target) __nanosleep(64);
        __threadfence();
    }
    __syncthreads();
}
__device__ __forceinline__ float sigmoidf_(float x) { return 1.0f / (1.0f + expf(-x)); }

// ============ init 1: x -> pre-swizzled bf16 hi/lo SW128 tiles ============
__global__ void cvt_x_kernel(const float* __restrict__ batch) {
    int bid = blockIdx.x;                 // t*16 + ch
    int tid = threadIdx.x;                // 128
    int b = tid >> 1, half = tid & 1;
    int t = bid >> 4, ch = bid & 15;
    const float* src = batch + ((size_t)t * BATCH + b) * DIN + ch * 64 + half * 32;
    unsigned char* dhi = g_zx + (size_t)bid * 16384;
    unsigned char* dlo = dhi + 8192;
    #pragma unroll
    for (int q = 0; q < 4; ++q) {
        float v[8];
        *(float4*)&v[0] = *(const float4*)(src + q * 8);
        *(float4*)&v[4] = *(const float4*)(src + q * 8 + 4);
        U4 hi, lo;
        #pragma unroll
        for (int j = 0; j < 8; ++j) bf16split(v[j], hi.s[j], lo.s[j]);
        uint32_t off = swz128((uint32_t)b * 128 + (uint32_t)(half * 4 + q) * 16);
        *(uint4*)(dhi + off) = hi.v;
        *(uint4*)(dlo + off) = lo.v;
    }
}

// ============ init 2 (FUSED): W_x tiles (bid<512) + W_h tiles (bid>=512) ============
__global__ void cvt_w_kernel(const float* __restrict__ Wi, const float* __restrict__ Wf,
                             const float* __restrict__ Wc, const float* __restrict__ Wo) {
    __shared__ float sraw[4][64][8];
    const float* Wsrc[4] = {Wi, Wf, Wc, Wo};
    int tid = threadIdx.x;                // 256
    if (blockIdx.x < 512) {
        int bid = blockIdx.x;             // ng*16 + ch
        int ng = bid >> 4, ch = bid & 15;
        int j = tid >> 1, khalf = tid & 1;
        int q = j >> 5, c = j & 31, gate = c >> 3;
        int wcol = (4 * ng + q) * 8 + (c & 7);
        const float* src = Wsrc[gate] + (size_t)(ch * 64 + khalf * 32) * DHID + wcol;
        unsigned char* dst = g_Wxt + (size_t)bid * 32768;
        #pragma unroll
        for (int qq = 0; qq < 4; ++qq) {
            U4 hi, lo;
            #pragma unroll
            for (int kk = 0; kk < 8; ++kk)
                bf16split(src[(size_t)(qq * 8 + kk) * DHID], hi.s[kk], lo.s[kk]);
            uint32_t off = swz128((uint32_t)j * 128 + (uint32_t)(khalf * 4 + qq) * 16);
            *(uint4*)(dst + off) = hi.v;
            *(uint4*)(dst + 16384 + off) = lo.v;
        }
    } else {
        int bid = blockIdx.x - 512;       // cta*16 + ch
        int cta = bid >> 4, ch = bid & 15;
        {
            int g = tid >> 6, kk = tid & 63;
            const float* s = Wsrc[g] + (size_t)(1024 + ch * 64 + kk) * DHID + cta * 8;
            float4 a = *(const float4*)s, b = *(const float4*)(s + 4);
            sraw[g][kk][0] = a.x; sraw[g][kk][1] = a.y; sraw[g][kk][2] = a.z; sraw[g][kk][3] = a.w;
            sraw[g][kk][4] = b.x; sraw[g][kk][5] = b.y; sraw[g][kk][6] = b.z; sraw[g][kk][7] = b.w;
        }
        __syncthreads();
        int c = tid >> 3, kkb = tid & 7;
        int g = c >> 3, dd = c & 7;
        U4 hi, lo;
        #pragma unroll
        for (int j = 0; j < 8; ++j) bf16split(sraw[g][kkb * 8 + j][dd], hi.s[j], lo.s[j]);
        unsigned char* dst = g_Wht + (size_t)bid * 8192;
        uint32_t off = swz128((uint32_t)c * 128 + (uint32_t)kkb * 16);
        *(uint4*)(dst + off) = hi.v;
        *(uint4*)(dst + 4096 + off) = lo.v;
    }
}

// ============ precompute GEMM: px[t][cta][b,32c] = x_t @ W_x (3-term split) ============
__global__ __launch_bounds__(256, 1)
void gemm_x_kernel() {
    extern __shared__ __align__(1024) unsigned char sm[];
    const uint32_t smem = smem_u32(sm);
    const int ng = blockIdx.x;
    const int tg = blockIdx.y;
    const int tid = threadIdx.x, wid = tid >> 5, lane = tid & 31;
    const int mt = wid & 3;
    const int nh = wid >> 2;
    const int lane16 = lane & 15;
    const int usel_a = lane >> 4;
    const int usel_b = (lane16 >> 3) & 1;

    int aoff[4][4];
    #pragma unroll
    for (int mi = 0; mi < 4; ++mi) {
        int arow = mi * 16 + lane16, arx = (arow & 7) << 4;
        #pragma unroll
        for (int ks = 0; ks < 4; ++ks)
            aoff[mi][ks] = arow * 128 + ((32 * ks + 16 * usel_a) ^ arx);
    }
    int boff[8][4];
    #pragma unroll
    for (int ni = 0; ni < 8; ++ni) {
        int brow = nh * 64 + ni * 8 + (lane16 & 7), brx = (brow & 7) << 4;
        #pragma unroll
        for (int ks = 0; ks < 4; ++ks)
            boff[ni][ks] = brow * 128 + ((32 * ks + 16 * usel_b) ^ brx);
    }

    float acc[4][8][4];
    #pragma unroll
    for (int mi = 0; mi < 4; ++mi)
        #pragma unroll
        for (int ni = 0; ni < 8; ++ni)
            #pragma unroll
            for (int q = 0; q < 4; ++q) acc[mi][ni][q] = 0.0f;

    auto issueP = [&](int ch) {
        uint32_t sb = smem + (uint32_t)(ch & 1) * PSTG_BYTES;
        #pragma unroll
        for (int i = 0; i < 16; ++i) {
            int j = tid + i * 256;
            int tt = j >> 10, off = j & 1023;
            cp16(sb + tt * 16384 + off * 16,
                 g_zx + ((size_t)(tg * 4 + tt) * 16 + ch) * 16384 + off * 16);
        }
        #pragma unroll
        for (int i = 0; i < 8; ++i) {
            int j = tid + i * 256;
            cp16(sb + 65536 + j * 16, g_Wxt + ((size_t)(ng * 16 + ch)) * 32768 + j * 16);
        }
        cp_commit();
    };

    issueP(0);
    for (int ch = 0; ch < 16; ++ch) {
        if (ch + 1 < 16) { issueP(ch + 1); cp_wait<1>(); }
        else             cp_wait<0>();
        __syncthreads();
        uint32_t sb  = smem + (uint32_t)(ch & 1) * PSTG_BYTES;
        uint32_t zhi = sb + mt * 16384, zlo = zhi + 8192;
        uint32_t bhi = sb + 65536, blo = bhi + 16384;
        #pragma unroll
        for (int ks = 0; ks < 4; ++ks) {
            uint32_t zh[4][4], zl[4][4], wf[8][2];
            #pragma unroll
            for (int mi = 0; mi < 4; ++mi) ldsm4(zh[mi][0], zh[mi][1], zh[mi][2], zh[mi][3], zhi + aoff[mi][ks]);
            #pragma unroll
            for (int ni = 0; ni < 8; ++ni) ldsm2(wf[ni][0], wf[ni][1], bhi + boff[ni][ks]);
            #pragma unroll
            for (int mi = 0; mi < 4; ++mi)
                #pragma unroll
                for (int ni = 0; ni < 8; ++ni)
                    mma16816(acc[mi][ni], zh[mi][0], zh[mi][1], zh[mi][2], zh[mi][3], wf[ni][0], wf[ni][1]);
            #pragma unroll
            for (int mi = 0; mi < 4; ++mi) ldsm4(zl[mi][0], zl[mi][1], zl[mi][2], zl[mi][3], zlo + aoff[mi][ks]);
            #pragma unroll
            for (int mi = 0; mi < 4; ++mi)
                #pragma unroll
                for (int ni = 0; ni < 8; ++ni)
                    mma16816(acc[mi][ni], zl[mi][0], zl[mi][1], zl[mi][2], zl[mi][3], wf[ni][0], wf[ni][1]);
            #pragma unroll
            for (int ni = 0; ni < 8; ++ni) ldsm2(wf[ni][0], wf[ni][1], blo + boff[ni][ks]);
            #pragma unroll
            for (int mi = 0; mi < 4; ++mi)
                #pragma unroll
                for (int ni = 0; ni < 8; ++ni)
                    mma16816(acc[mi][ni], zh[mi][0], zh[mi][1], zh[mi][2], zh[mi][3], wf[ni][0], wf[ni][1]);
        }
        __syncthreads();
    }

    const int t = tg * 4 + mt;
    #pragma unroll
    for (int mi = 0; mi < 4; ++mi) {
        int r0 = mi * 16 + (lane >> 2);
        #pragma unroll
        for (int ni = 0; ni < 8; ++ni) {
            int j = nh * 64 + ni * 8 + (lane & 3) * 2;
            int q = j >> 5, c = j & 31;
            float* base = g_px + ((size_t)t * NCTA + 4 * ng + q) * PX_ROWB;
            base[r0 * 33 + c]           = acc[mi][ni][0];
            base[r0 * 33 + c + 1]       = acc[mi][ni][1];
            base[(r0 + 8) * 33 + c]     = acc[mi][ni][2];
            base[(r0 + 8) * 33 + c + 1] = acc[mi][ni][3];
        }
    }
}

// ============ h tile writer (init only; epilogue writes per-thread) ============
__device__ __forceinline__ void store_h_tiles(int nbuf, int cta, int b, const float* h8) {
    int chl = cta >> 3, kkb = cta & 7;
    U4 hi, lo;
    #pragma unroll
    for (int j = 0; j < 8; ++j) bf16split(h8[j], hi.s[j], lo.s[j]);
    uint32_t off = swz128((uint32_t)b * 128 + (uint32_t)kkb * 16);
    unsigned char* base = g_zh + ((size_t)nbuf * 16 + chl) * 16384;
    *(uint4*)(base + off) = hi.v;
    *(uint4*)(base + 8192 + off) = lo.v;
}

// ============ persistent recurrent kernel: K=128 chunks, K-split-8 ============
__global__ __launch_bounds__(NTHR, 1)
void lstm_mma_kernel(const int* __restrict__ lengths, const float* __restrict__ c0,
                     const float* __restrict__ bi, const float* __restrict__ bff,
                     const float* __restrict__ bc, const float* __restrict__ bo,
                     float* __restrict__ out) {
    extern __shared__ __align__(1024) unsigned char sm[];
    const uint32_t smem = smem_u32(sm);
    float* pp_s   = (float*)sm;                // [8][2176] floats — ALIASES stage region
    float* c_s    = (float*)(sm + C_OFF);      // [512]
    float* bias_s = (float*)(sm + BIAS_OFF);   // [32]
    int*   len_s  = (int*)(sm + LEN_OFF);      // [64]
    volatile unsigned long long* tgt_s = (volatile unsigned long long*)(sm + TGT_OFF);

    const int tid = threadIdx.x, wid = tid >> 5, lane = tid & 31;
    const int cta = blockIdx.x;
    const int dbase = cta * 8;

    // warp = k16-residue: sub-64-chunk sc = wid>>2, inner k-step ks4 = wid&3
    const int sc = wid >> 2, ks4 = wid & 3;
    const int lane16 = lane & 15;
    const int usel_a = lane >> 4;
    const int usel_b = (lane16 >> 3) & 1;
    int aoff[4], boff[4];
    #pragma unroll
    for (int mi = 0; mi < 4; ++mi) {
        int arow = mi * 16 + lane16, arx = (arow & 7) << 4;
        aoff[mi] = arow * 128 + ((32 * ks4 + 16 * usel_a) ^ arx);
    }
    #pragma unroll
    for (int ni = 0; ni < 4; ++ni) {
        int brow = ni * 8 + (lane16 & 7), brx = (brow & 7) << 4;
        boff[ni] = brow * 128 + ((32 * ks4 + 16 * usel_b) ^ brx);
    }

    // epilogue coordinates
    const int b = tid >> 2, dd0 = (tid & 3) * 2;
    const int chl = cta >> 3, kkb = cta & 7;

    // ---- init: W_h -> SMEM (resident) ----
    {
        const unsigned char* wsrc = g_Wht + (size_t)cta * (16 * 8192);
        for (int i = tid; i < 8192; i += NTHR) cp16(smem + WOFF + i * 16, wsrc + (size_t)i * 16);
        cp_commit(); cp_wait<0>();
    }
    for (int j = tid; j < 512; j += NTHR) c_s[j] = c0[dbase + (j & 7)];
    if (tid < 32) bias_s[tid] = ((tid >> 3) == 0 ? bi : (tid >> 3) == 1 ? bff :
                                 (tid >> 3) == 2 ? bc : bo)[dbase + (tid & 7)];
    if (tid < BATCH) {
        len_s[tid] = lengths[tid];
        float h0[8];
        #pragma unroll
        for (int dd = 0; dd < 8; ++dd) h0[dd] = tanhf(c0[dbase + dd]);
        store_h_tiles(0, cta, tid, h0);
    }
    if (tid == 0) *tgt_s = 0ULL;   // step-0 wait passes immediately
    grid_sync_full();

    // ---- recurrence ----
    for (int t = 0; t < TSTEPS; ++t) {
        const int buf = t & 1;

        // px prefetch into registers (no h dependency; consumed at epilogue)
        float pxr[8];
        {
            const float* p = g_px + ((size_t)t * NCTA + cta) * PX_ROWB + b * 33 + dd0;
            #pragma unroll
            for (int g = 0; g < 4; ++g) {
                pxr[g * 2]     = __ldg(p + g * 8);
                pxr[g * 2 + 1] = __ldg(p + g * 8 + 1);
            }
        }

        // wait for all CTAs' step t-1 h
        if (tid == 0) {
            unsigned long long tgt = *tgt_s;
            while (*(volatile unsigned long long*)&g_bar < tgt) __nanosleep(32);
            __threadfence();
        }
        __syncthreads();

        // stage a 128-K chunk: two 64-k h tiles -> [Ahi][Bhi][Alo][Blo]
        auto issue = [&](int ci) {
            const unsigned char* srcA = g_zh + ((size_t)buf * 16 + 2 * ci) * 16384;
            uint32_t sb = smem + (uint32_t)(ci % NSTG) * ZSTG;
            #pragma unroll
            for (int i = 0; i < 8; ++i) {
                int j = tid + i * NTHR;            // 0..2047
                int part = j >> 9;                 // 0=Ahi 1=Alo 2=Bhi 3=Blo
                uint32_t off = (uint32_t)(j & 511) * 16;
                const unsigned char* src = srcA + (size_t)(part >> 1) * 16384 + (part & 1) * 8192 + off;
                uint32_t dst = sb + (uint32_t)(part & 1) * 16384 + (uint32_t)(part >> 1) * 8192 + off;
                cp16(dst, src);
            }
            cp_commit();
        };

        float acc[4][4][4];
        #pragma unroll
        for (int mi = 0; mi < 4; ++mi)
            #pragma unroll
            for (int ni = 0; ni < 4; ++ni)
                #pragma unroll
                for (int q = 0; q < 4; ++q) acc[mi][ni][q] = 0.0f;

        issue(0); issue(1);
        for (int ch = 0; ch < NCHB; ++ch) {
            if (ch < NCHB - 1) cp_wait<1>();
            else               cp_wait<0>();
            __syncthreads();
            if (ch + 2 < NCHB) issue(ch + 2);   // post-sync: freed stage is safe to refill

            const uint32_t sb  = smem + (uint32_t)(ch % NSTG) * ZSTG;
            const uint32_t zhi = sb + (uint32_t)sc * 8192;
            const uint32_t zlo = zhi + 16384;
            const uint32_t whi = smem + WOFF + (uint32_t)(2 * ch + sc) * 8192;
            const uint32_t wlo = whi + 4096;

            uint32_t ah[4][4], al[4][4], bh[4][2], bl[4][2];
            #pragma unroll
            for (int mi = 0; mi < 4; ++mi) {
                ldsm4(ah[mi][0], ah[mi][1], ah[mi][2], ah[mi][3], zhi + aoff[mi]);
                ldsm4(al[mi][0], al[mi][1], al[mi][2], al[mi][3], zlo + aoff[mi]);
            }
            #pragma unroll
            for (int ni = 0; ni < 4; ++ni) {
                ldsm2(bh[ni][0], bh[ni][1], whi + boff[ni]);
                ldsm2(bl[ni][0], bl[ni][1], wlo + boff[ni]);
            }
            #pragma unroll
            for (int mi = 0; mi < 4; ++mi)
                #pragma unroll
                for (int ni = 0; ni < 4; ++ni) {
                    mma16816(acc[mi][ni], ah[mi][0], ah[mi][1], ah[mi][2], ah[mi][3], bh[ni][0], bh[ni][1]);
                    mma16816(acc[mi][ni], ah[mi][0], ah[mi][1], ah[mi][2], ah[mi][3], bl[ni][0], bl[ni][1]);
                    mma16816(acc[mi][ni], al[mi][0], al[mi][1], al[mi][2], al[mi][3], bh[ni][0], bh[ni][1]);
                }
        }
        __syncthreads();   // all stage reads done before pp aliases the region

        // ---- gather K-split partials (warp wid owns slice wid; stride 34 = aligned float2) ----
        {
            float* pp = pp_s + wid * PP_SLICE;
            #pragma unroll
            for (int mi = 0; mi < 4; ++mi) {
                int r0 = mi * 16 + (lane >> 2);
                #pragma unroll
                for (int ni = 0; ni < 4; ++ni) {
                    int c = ni * 8 + (lane & 3) * 2;
                    *(float2*)&pp[r0 * PP_STRIDE + c]       = make_float2(acc[mi][ni][0], acc[mi][ni][1]);
                    *(float2*)&pp[(r0 + 8) * PP_STRIDE + c] = make_float2(acc[mi][ni][2], acc[mi][ni][3]);
                }
            }
        }
        __syncthreads();

        // ---- epilogue: all 256 threads, 2 cells each; out-store deferred past the arrive ----
        float h2[2];
        {
            const int myl = len_s[b];
            const int bo34 = b * PP_STRIDE;
            unsigned short hhw[2], hlw[2];
            #pragma unroll
            for (int r = 0; r < 2; ++r) {
                const int dd = dd0 + r;
                float pre[4];
                #pragma unroll
                for (int g = 0; g < 4; ++g) {
                    const int c = g * 8 + dd;
                    float s = pxr[g * 2 + r] + bias_s[c];
                    #pragma unroll
                    for (int sl = 0; sl < 8; ++sl) s += pp_s[sl * PP_SLICE + bo34 + c];
                    pre[g] = s;
                }
                float ig = sigmoidf_(pre[0]), fg = sigmoidf_(pre[1]);
                float gg = tanhf(pre[2]),     og = sigmoidf_(pre[3]);
                float cn = fg * c_s[b * 8 + dd] + ig * gg;
                float h  = og * tanhf(cn);
                if (t >= myl) h = 0.0f;
                c_s[b * 8 + dd] = cn;
                __nv_bfloat16 hb = __float2bfloat16_rn(h);
                hhw[r] = reinterpret_cast<unsigned short&>(hb);
                hlw[r] = bf16hi(h - __bfloat162float(hb));
                h2[r] = h;
            }
            // h pair -> global tiles (hi/lo) — what other CTAs wait on
            unsigned char* base = g_zh + ((size_t)(buf ^ 1) * 16 + chl) * 16384;
            uint32_t off = swz128((uint32_t)b * 128 + (uint32_t)kkb * 16) + (uint32_t)dd0 * 2;
            *(uint32_t*)(base + off)        = (uint32_t)hhw[0] | ((uint32_t)hhw[1] << 16);
            *(uint32_t*)(base + 8192 + off) = (uint32_t)hlw[0] | ((uint32_t)hlw[1] << 16);
        }
        __syncthreads();
        if (tid == 0) {        // producer arrive (post-sync tid0 fence covers all threads' h stores)
            __threadfence();
            unsigned long long my = atomicAdd(&g_bar, 1ULL);
            *tgt_s = (my / NCTA + 1ULL) * NCTA;
        }
        // output store: off the inter-CTA critical path
        *(float2*)(out + ((size_t)t * BATCH + b) * DHID + dbase + dd0) = make_float2(h2[0], h2[1]);
    }
}

extern "C" void kernel_launch(void* const* d_in, const int* in_sizes, int n_in,
                              void* d_out, int out_size) {
    const float* batch   = (const float*)d_in[0];
    const int*   lengths = (const int*)  d_in[1];
    const float* c0      = (const float*)d_in[2];
    const float* Wi = (const float*)d_in[3];
    const float* bi = (const float*)d_in[4];
    const float* Wf = (const float*)d_in[5];
    const float* bf = (const float*)d_in[6];
    const float* Wc = (const float*)d_in[7];
    const float* bc = (const float*)d_in[8];
    const float* Wo = (const float*)d_in[9];
    const float* bo = (const float*)d_in[10];
    float* out = (float*)d_out;

    cvt_x_kernel<<<TSTEPS * 16, 128>>>(batch);
    cvt_w_kernel<<<512 + NCTA * 16, 256>>>(Wi, Wf, Wc, Wo);

    cudaFuncSetAttribute(gemm_x_kernel, cudaFuncAttributeMaxDynamicSharedMemorySize, SMEM_PRE);
    gemm_x_kernel<<<dim3(32, 128), 256, SMEM_PRE>>>();

    cudaFuncSetAttribute(lstm_mma_kernel, cudaFuncAttributeMaxDynamicSharedMemorySize, SMEM_LOOP);
    lstm_mma_kernel<<<NCTA, NTHR, SMEM_LOOP>>>(lengths, c0, bi, bf, bc, bo, out);
}

// round 13
// speedup vs baseline: 2.0017x; 1.0706x over previous
#include <cuda_runtime.h>
#include <cuda_bf16.h>
#include <cstdint>
#include <math.h>

// ---------------- problem constants ----------------
#define TSTEPS 512
#define BATCH  64
#define DIN    1024
#define DHID   1024

// ---------------- persistent-loop config ----------------
#define NCTA 128                 // persistent CTAs; CTA owns 8 hidden dims = 32 gemm cols
#define NTHR 512                 // 16 warps: mg = wid&3 (m16 group), kslice = wid>>2
#define NCHL 16                  // recurrent K chunks (1024/64)

// loop SMEM layout (bytes)
#define ZSTG    16384            // per stage: zhi 8K | zlo 8K
#define NSTG    3
#define WOFF    (NSTG * ZSTG)                // 49152 : W_h resident 128KB
#define PP_STRIDE 34
#define PP_SLICE  (BATCH * PP_STRIDE)        // 2176 floats per k-slice
#define PP_OFF  (WOFF + 131072)              // 180224: pre_part [4][2176] floats = 34816
#define C_OFF   (PP_OFF + 34816)             // 215040: c state 512 floats
#define BIAS_OFF (C_OFF + 2048)              // 217088: 32 floats
#define LEN_OFF (BIAS_OFF + 128)             // 217216: 64 ints
#define TGT_OFF (LEN_OFF + 256)              // 217472
#define SMEM_LOOP (TGT_OFF + 16)             // 217488

// precompute GEMM smem: 2 stages x (A 4x16KB + B 32KB)
#define PSTG_BYTES 98304
#define SMEM_PRE   (2 * PSTG_BYTES)

#define PX_ROWB 2112             // floats per (t,cta) px block: 64 rows x 33

// ---------------- device-global scratch (static; no cudaMalloc) ----------------
__device__ __align__(16) unsigned char g_zx[(size_t)TSTEPS*16*16384];  // x tiles [t*16+ch][hi8K|lo8K]
__device__ __align__(16) unsigned char g_zh[(size_t)2*16*16384];       // h tiles [buf*16+chl][hi8K|lo8K]
__device__ __align__(16) unsigned char g_Wxt[(size_t)32*16*32768];     // Wx tiles [ng*16+ch][hi16K|lo16K]
__device__ __align__(16) unsigned char g_Wht[(size_t)NCTA*NCHL*8192];  // Wh tiles [cta*16+ch][hi4K|lo4K]
__device__ float g_px[(size_t)TSTEPS*NCTA*PX_ROWB];                    // x-projection [t][cta][b*33+c]
__device__ unsigned long long g_bar;   // monotonic grid-barrier ticket

// ---------------- helpers ----------------
__host__ __device__ __forceinline__ uint32_t swz128(uint32_t x) { return x ^ ((x >> 3) & 0x70); }

__device__ __forceinline__ uint32_t smem_u32(const void* p) {
    uint32_t a;
    asm("{ .reg .u64 t; cvta.to.shared.u64 t, %1; cvt.u32.u64 %0, t; }" : "=r"(a) : "l"(p));
    return a;
}
union U4 { unsigned short s[8]; uint4 v; };
__device__ __forceinline__ void bf16split(float v, unsigned short& hi, unsigned short& lo) {
    __nv_bfloat16 h = __float2bfloat16_rn(v);
    float r = v - __bfloat162float(h);
    __nv_bfloat16 l = __float2bfloat16_rn(r);
    hi = reinterpret_cast<unsigned short&>(h);
    lo = reinterpret_cast<unsigned short&>(l);
}
__device__ __forceinline__ unsigned short bf16hi(float v) {
    __nv_bfloat16 h = __float2bfloat16_rn(v);
    return reinterpret_cast<unsigned short&>(h);
}
__device__ __forceinline__ void cp16(uint32_t saddr, const void* gaddr) {
    asm volatile("cp.async.cg.shared.global [%0], [%1], 16;" :: "r"(saddr), "l"(gaddr));
}
__device__ __forceinline__ void cp_commit() { asm volatile("cp.async.commit_group;"); }
template <int N> __device__ __forceinline__ void cp_wait() {
    asm volatile("cp.async.wait_group %0;" :: "n"(N));
}
__device__ __forceinline__ void ldsm4(uint32_t& r0, uint32_t& r1, uint32_t& r2, uint32_t& r3, uint32_t a) {
    asm volatile("ldmatrix.sync.aligned.m8n8.x4.shared.b16 {%0,%1,%2,%3}, [%4];"
                 : "=r"(r0), "=r"(r1), "=r"(r2), "=r"(r3) : "r"(a));
}
__device__ __forceinline__ void ldsm2(uint32_t& r0, uint32_t& r1, uint32_t a) {
    asm volatile("ldmatrix.sync.aligned.m8n8.x2.shared.b16 {%0,%1}, [%2];"
                 : "=r"(r0), "=r"(r1) : "r"(a));
}
__device__ __forceinline__ void mma16816(float* d, uint32_t a0, uint32_t a1, uint32_t a2, uint32_t a3,
                                         uint32_t b0, uint32_t b1) {
    asm volatile("mma.sync.aligned.m16n8k16.row.col.f32.bf16.bf16.f32 "
                 "{%0,%1,%2,%3}, {%4,%5,%6,%7}, {%8,%9}, {%0,%1,%2,%3};"
                 : "+f"(d[0]), "+f"(d[1]), "+f"(d[2]), "+f"(d[3])
                 : "r"(a0), "r"(a1), "r"(a2), "r"(a3), "r"(b0), "r"(b1));
}
__device__ __forceinline__ void grid_sync_full() {
    __syncthreads();
    if (threadIdx.x == 0) {
        __threadfence();
        unsigned long long t = atomicAdd(&g_bar, 1ULL);
        unsigned long long target = (t / NCTA + 1ULL) * NCTA;
        while (*(volatile unsigned long long*)&g_bar < target) __nanosleep(64);
        __threadfence();
    }
    __syncthreads();
}
__device__ __forceinline__ float sigmoidf_(float x) { return 1.0f / (1.0f + expf(-x)); }

// ============ init 1: x -> pre-swizzled bf16 hi/lo SW128 tiles ============
__global__ void cvt_x_kernel(const float* __restrict__ batch) {
    int bid = blockIdx.x;                 // t*16 + ch
    int tid = threadIdx.x;                // 128
    int b = tid >> 1, half = tid & 1;
    int t = bid >> 4, ch = bid & 15;
    const float* src = batch + ((size_t)t * BATCH + b) * DIN + ch * 64 + half * 32;
    unsigned char* dhi = g_zx + (size_t)bid * 16384;
    unsigned char* dlo = dhi + 8192;
    #pragma unroll
    for (int q = 0; q < 4; ++q) {
        float v[8];
        *(float4*)&v[0] = *(const float4*)(src + q * 8);
        *(float4*)&v[4] = *(const float4*)(src + q * 8 + 4);
        U4 hi, lo;
        #pragma unroll
        for (int j = 0; j < 8; ++j) bf16split(v[j], hi.s[j], lo.s[j]);
        uint32_t off = swz128((uint32_t)b * 128 + (uint32_t)(half * 4 + q) * 16);
        *(uint4*)(dhi + off) = hi.v;
        *(uint4*)(dlo + off) = lo.v;
    }
}

// ============ init 2 (FUSED): W_x tiles (bid<512) + W_h tiles (bid>=512) ============
__global__ void cvt_w_kernel(const float* __restrict__ Wi, const float* __restrict__ Wf,
                             const float* __restrict__ Wc, const float* __restrict__ Wo) {
    __shared__ float sraw[4][64][8];
    const float* Wsrc[4] = {Wi, Wf, Wc, Wo};
    int tid = threadIdx.x;                // 256
    if (blockIdx.x < 512) {
        int bid = blockIdx.x;             // ng*16 + ch
        int ng = bid >> 4, ch = bid & 15;
        int j = tid >> 1, khalf = tid & 1;
        int q = j >> 5, c = j & 31, gate = c >> 3;
        int wcol = (4 * ng + q) * 8 + (c & 7);
        const float* src = Wsrc[gate] + (size_t)(ch * 64 + khalf * 32) * DHID + wcol;
        unsigned char* dst = g_Wxt + (size_t)bid * 32768;
        #pragma unroll
        for (int qq = 0; qq < 4; ++qq) {
            U4 hi, lo;
            #pragma unroll
            for (int kk = 0; kk < 8; ++kk)
                bf16split(src[(size_t)(qq * 8 + kk) * DHID], hi.s[kk], lo.s[kk]);
            uint32_t off = swz128((uint32_t)j * 128 + (uint32_t)(khalf * 4 + qq) * 16);
            *(uint4*)(dst + off) = hi.v;
            *(uint4*)(dst + 16384 + off) = lo.v;
        }
    } else {
        int bid = blockIdx.x - 512;       // cta*16 + ch
        int cta = bid >> 4, ch = bid & 15;
        {
            int g = tid >> 6, kk = tid & 63;
            const float* s = Wsrc[g] + (size_t)(1024 + ch * 64 + kk) * DHID + cta * 8;
            float4 a = *(const float4*)s, b = *(const float4*)(s + 4);
            sraw[g][kk][0] = a.x; sraw[g][kk][1] = a.y; sraw[g][kk][2] = a.z; sraw[g][kk][3] = a.w;
            sraw[g][kk][4] = b.x; sraw[g][kk][5] = b.y; sraw[g][kk][6] = b.z; sraw[g][kk][7] = b.w;
        }
        __syncthreads();
        int c = tid >> 3, kkb = tid & 7;
        int g = c >> 3, dd = c & 7;
        U4 hi, lo;
        #pragma unroll
        for (int j = 0; j < 8; ++j) bf16split(sraw[g][kkb * 8 + j][dd], hi.s[j], lo.s[j]);
        unsigned char* dst = g_Wht + (size_t)bid * 8192;
        uint32_t off = swz128((uint32_t)c * 128 + (uint32_t)kkb * 16);
        *(uint4*)(dst + off) = hi.v;
        *(uint4*)(dst + 4096 + off) = lo.v;
    }
}

// ============ precompute GEMM: px[t][cta][b,32c] = x_t @ W_x (3-term split) ============
__global__ __launch_bounds__(256, 1)
void gemm_x_kernel() {
    extern __shared__ __align__(1024) unsigned char sm[];
    const uint32_t smem = smem_u32(sm);
    const int ng = blockIdx.x;
    const int tg = blockIdx.y;
    const int tid = threadIdx.x, wid = tid >> 5, lane = tid & 31;
    const int mt = wid & 3;
    const int nh = wid >> 2;
    const int lane16 = lane & 15;
    const int usel_a = lane >> 4;
    const int usel_b = (lane16 >> 3) & 1;

    int aoff[4][4];
    #pragma unroll
    for (int mi = 0; mi < 4; ++mi) {
        int arow = mi * 16 + lane16, arx = (arow & 7) << 4;
        #pragma unroll
        for (int ks = 0; ks < 4; ++ks)
            aoff[mi][ks] = arow * 128 + ((32 * ks + 16 * usel_a) ^ arx);
    }
    int boff[8][4];
    #pragma unroll
    for (int ni = 0; ni < 8; ++ni) {
        int brow = nh * 64 + ni * 8 + (lane16 & 7), brx = (brow & 7) << 4;
        #pragma unroll
        for (int ks = 0; ks < 4; ++ks)
            boff[ni][ks] = brow * 128 + ((32 * ks + 16 * usel_b) ^ brx);
    }

    float acc[4][8][4];
    #pragma unroll
    for (int mi = 0; mi < 4; ++mi)
        #pragma unroll
        for (int ni = 0; ni < 8; ++ni)
            #pragma unroll
            for (int q = 0; q < 4; ++q) acc[mi][ni][q] = 0.0f;

    auto issueP = [&](int ch) {
        uint32_t sb = smem + (uint32_t)(ch & 1) * PSTG_BYTES;
        #pragma unroll
        for (int i = 0; i < 16; ++i) {
            int j = tid + i * 256;
            int tt = j >> 10, off = j & 1023;
            cp16(sb + tt * 16384 + off * 16,
                 g_zx + ((size_t)(tg * 4 + tt) * 16 + ch) * 16384 + off * 16);
        }
        #pragma unroll
        for (int i = 0; i < 8; ++i) {
            int j = tid + i * 256;
            cp16(sb + 65536 + j * 16, g_Wxt + ((size_t)(ng * 16 + ch)) * 32768 + j * 16);
        }
        cp_commit();
    };

    issueP(0);
    for (int ch = 0; ch < 16; ++ch) {
        if (ch + 1 < 16) { issueP(ch + 1); cp_wait<1>(); }
        else             cp_wait<0>();
        __syncthreads();
        uint32_t sb  = smem + (uint32_t)(ch & 1) * PSTG_BYTES;
        uint32_t zhi = sb + mt * 16384, zlo = zhi + 8192;
        uint32_t bhi = sb + 65536, blo = bhi + 16384;
        #pragma unroll
        for (int ks = 0; ks < 4; ++ks) {
            uint32_t zh[4][4], zl[4][4], wf[8][2];
            #pragma unroll
            for (int mi = 0; mi < 4; ++mi) ldsm4(zh[mi][0], zh[mi][1], zh[mi][2], zh[mi][3], zhi + aoff[mi][ks]);
            #pragma unroll
            for (int ni = 0; ni < 8; ++ni) ldsm2(wf[ni][0], wf[ni][1], bhi + boff[ni][ks]);
            #pragma unroll
            for (int mi = 0; mi < 4; ++mi)
                #pragma unroll
                for (int ni = 0; ni < 8; ++ni)
                    mma16816(acc[mi][ni], zh[mi][0], zh[mi][1], zh[mi][2], zh[mi][3], wf[ni][0], wf[ni][1]);
            #pragma unroll
            for (int mi = 0; mi < 4; ++mi) ldsm4(zl[mi][0], zl[mi][1], zl[mi][2], zl[mi][3], zlo + aoff[mi][ks]);
            #pragma unroll
            for (int mi = 0; mi < 4; ++mi)
                #pragma unroll
                for (int ni = 0; ni < 8; ++ni)
                    mma16816(acc[mi][ni], zl[mi][0], zl[mi][1], zl[mi][2], zl[mi][3], wf[ni][0], wf[ni][1]);
            #pragma unroll
            for (int ni = 0; ni < 8; ++ni) ldsm2(wf[ni][0], wf[ni][1], blo + boff[ni][ks]);
            #pragma unroll
            for (int mi = 0; mi < 4; ++mi)
                #pragma unroll
                for (int ni = 0; ni < 8; ++ni)
                    mma16816(acc[mi][ni], zh[mi][0], zh[mi][1], zh[mi][2], zh[mi][3], wf[ni][0], wf[ni][1]);
        }
        __syncthreads();
    }

    const int t = tg * 4 + mt;
    #pragma unroll
    for (int mi = 0; mi < 4; ++mi) {
        int r0 = mi * 16 + (lane >> 2);
        #pragma unroll
        for (int ni = 0; ni < 8; ++ni) {
            int j = nh * 64 + ni * 8 + (lane & 3) * 2;
            int q = j >> 5, c = j & 31;
            float* base = g_px + ((size_t)t * NCTA + 4 * ng + q) * PX_ROWB;
            base[r0 * 33 + c]           = acc[mi][ni][0];
            base[r0 * 33 + c + 1]       = acc[mi][ni][1];
            base[(r0 + 8) * 33 + c]     = acc[mi][ni][2];
            base[(r0 + 8) * 33 + c + 1] = acc[mi][ni][3];
        }
    }
}

// ============ h tile writer (init only; epilogue writes per-thread) ============
__device__ __forceinline__ void store_h_tiles(int nbuf, int cta, int b, const float* h8) {
    int chl = cta >> 3, kkb = cta & 7;
    U4 hi, lo;
    #pragma unroll
    for (int j = 0; j < 8; ++j) bf16split(h8[j], hi.s[j], lo.s[j]);
    uint32_t off = swz128((uint32_t)b * 128 + (uint32_t)kkb * 16);
    unsigned char* base = g_zh + ((size_t)nbuf * 16 + chl) * 16384;
    *(uint4*)(base + off) = hi.v;
    *(uint4*)(base + 8192 + off) = lo.v;
}

// ============ persistent recurrent kernel: 16 warps, K=64 chunks, m-split-4 x K-split-4 ============
__global__ __launch_bounds__(NTHR, 1)
void lstm_mma_kernel(const int* __restrict__ lengths, const float* __restrict__ c0,
                     const float* __restrict__ bi, const float* __restrict__ bff,
                     const float* __restrict__ bc, const float* __restrict__ bo,
                     float* __restrict__ out) {
    extern __shared__ __align__(1024) unsigned char sm[];
    const uint32_t smem = smem_u32(sm);
    float* pp_s   = (float*)(sm + PP_OFF);     // [4][64*34]
    float* c_s    = (float*)(sm + C_OFF);      // [512]
    float* bias_s = (float*)(sm + BIAS_OFF);   // [32]
    int*   len_s  = (int*)(sm + LEN_OFF);      // [64]
    volatile unsigned long long* tgt_s = (volatile unsigned long long*)(sm + TGT_OFF);

    const int tid = threadIdx.x, wid = tid >> 5, lane = tid & 31;
    const int cta = blockIdx.x;
    const int dbase = cta * 8;

    // warp roles: mg = m16 group (0..3), kslice = k16 residue (0..3)
    const int mg = wid & 3, kslice = wid >> 2;
    const int lane16 = lane & 15;
    const int usel_a = lane >> 4;
    const int usel_b = (lane16 >> 3) & 1;
    int aoff, boff[4];
    {
        int arow = mg * 16 + lane16, arx = (arow & 7) << 4;
        aoff = arow * 128 + ((32 * kslice + 16 * usel_a) ^ arx);
    }
    #pragma unroll
    for (int ni = 0; ni < 4; ++ni) {
        int brow = ni * 8 + (lane16 & 7), brx = (brow & 7) << 4;
        boff[ni] = brow * 128 + ((32 * kslice + 16 * usel_b) ^ brx);
    }

    // epilogue coordinates: 1 cell per thread
    const int b = tid >> 3, dd = tid & 7;
    const int chl = cta >> 3, kkb = cta & 7;

    // ---- init: W_h -> SMEM (resident) ----
    {
        const unsigned char* wsrc = g_Wht + (size_t)cta * (NCHL * 8192);
        for (int i = tid; i < 8192; i += NTHR) cp16(smem + WOFF + i * 16, wsrc + (size_t)i * 16);
        cp_commit(); cp_wait<0>();
    }
    for (int j = tid; j < 512; j += NTHR) c_s[j] = c0[dbase + (j & 7)];
    if (tid < 32) bias_s[tid] = ((tid >> 3) == 0 ? bi : (tid >> 3) == 1 ? bff :
                                 (tid >> 3) == 2 ? bc : bo)[dbase + (tid & 7)];
    if (tid < BATCH) {
        len_s[tid] = lengths[tid];
        float h0[8];
        #pragma unroll
        for (int d = 0; d < 8; ++d) h0[d] = tanhf(c0[dbase + d]);
        store_h_tiles(0, cta, tid, h0);
    }
    if (tid == 0) *tgt_s = 0ULL;   // step-0 wait passes immediately
    grid_sync_full();

    // ---- recurrence ----
    for (int t = 0; t < TSTEPS; ++t) {
        const int buf = t & 1;

        // px prefetch into registers (no h dependency; consumed ~8us later at epilogue)
        float pxr[4];
        {
            const float* p = g_px + ((size_t)t * NCTA + cta) * PX_ROWB + b * 33 + dd;
            #pragma unroll
            for (int g = 0; g < 4; ++g) pxr[g] = __ldg(p + g * 8);
        }

        // wait for all CTAs' step t-1 h (tid0 poll + fence, block consumer pattern)
        if (tid == 0) {
            unsigned long long tgt = *tgt_s;
            while (*(volatile unsigned long long*)&g_bar < tgt) __nanosleep(32);
            __threadfence();
        }
        __syncthreads();

        auto issue = [&](int ci) {
            const unsigned char* srcz = g_zh + ((size_t)buf * 16 + ci) * 16384;
            uint32_t sb = smem + (uint32_t)(ci % NSTG) * ZSTG;
            #pragma unroll
            for (int i = 0; i < 2; ++i) {
                int j = tid + i * NTHR;
                cp16(sb + j * 16, srcz + (size_t)j * 16);
            }
            cp_commit();
        };

        float acc[4][4];
        #pragma unroll
        for (int ni = 0; ni < 4; ++ni)
            #pragma unroll
            for (int q = 0; q < 4; ++q) acc[ni][q] = 0.0f;

        issue(0); issue(1);
        for (int ch = 0; ch < NCHL; ++ch) {
            if (ch < NCHL - 1) cp_wait<1>();
            else               cp_wait<0>();
            __syncthreads();
            if (ch + 2 < NCHL) issue(ch + 2);   // post-sync: freed stage is safe to refill

            const uint32_t zb  = smem + (uint32_t)(ch % NSTG) * ZSTG;
            const uint32_t zhi = zb, zlo = zb + 8192;
            const uint32_t whi = smem + WOFF + (uint32_t)ch * 8192, wlo = whi + 4096;

            uint32_t ah[4], al[4], bh[4][2], bl[4][2];
            ldsm4(ah[0], ah[1], ah[2], ah[3], zhi + aoff);
            ldsm4(al[0], al[1], al[2], al[3], zlo + aoff);
            #pragma unroll
            for (int ni = 0; ni < 4; ++ni) {
                ldsm2(bh[ni][0], bh[ni][1], whi + boff[ni]);
                ldsm2(bl[ni][0], bl[ni][1], wlo + boff[ni]);
            }
            #pragma unroll
            for (int ni = 0; ni < 4; ++ni) {
                mma16816(acc[ni], ah[0], ah[1], ah[2], ah[3], bh[ni][0], bh[ni][1]);
                mma16816(acc[ni], ah[0], ah[1], ah[2], ah[3], bl[ni][0], bl[ni][1]);
                mma16816(acc[ni], al[0], al[1], al[2], al[3], bh[ni][0], bh[ni][1]);
            }
        }

        // ---- gather K-split partials (warp-private slices; stride 34 = aligned float2) ----
        {
            float* pp = pp_s + kslice * PP_SLICE;
            int r0 = mg * 16 + (lane >> 2);
            #pragma unroll
            for (int ni = 0; ni < 4; ++ni) {
                int c = ni * 8 + (lane & 3) * 2;
                *(float2*)&pp[r0 * PP_STRIDE + c]       = make_float2(acc[ni][0], acc[ni][1]);
                *(float2*)&pp[(r0 + 8) * PP_STRIDE + c] = make_float2(acc[ni][2], acc[ni][3]);
            }
        }
        __syncthreads();

        // ---- epilogue: 512 threads, 1 cell each; out-store deferred past the arrive ----
        float hval;
        {
            const int myl = len_s[b];
            const int bo34 = b * PP_STRIDE;
            float pre[4];
            #pragma unroll
            for (int g = 0; g < 4; ++g) {
                const int c = g * 8 + dd;
                pre[g] = pxr[g] + bias_s[c]
                       + pp_s[bo34 + c] + pp_s[PP_SLICE + bo34 + c]
                       + pp_s[2 * PP_SLICE + bo34 + c] + pp_s[3 * PP_SLICE + bo34 + c];
            }
            float ig = sigmoidf_(pre[0]), fg = sigmoidf_(pre[1]);
            float gg = tanhf(pre[2]),     og = sigmoidf_(pre[3]);
            float cn = fg * c_s[b * 8 + dd] + ig * gg;
            float h  = og * tanhf(cn);
            if (t >= myl) h = 0.0f;
            c_s[b * 8 + dd] = cn;
            __nv_bfloat16 hb = __float2bfloat16_rn(h);
            unsigned short hh = reinterpret_cast<unsigned short&>(hb);
            unsigned short hl = bf16hi(h - __bfloat162float(hb));
            hval = h;
            // h -> global tiles (hi/lo), 2-byte stores
            unsigned char* base = g_zh + ((size_t)(buf ^ 1) * 16 + chl) * 16384;
            uint32_t off = swz128((uint32_t)b * 128 + (uint32_t)kkb * 16) + (uint32_t)dd * 2;
            *(unsigned short*)(base + off)        = hh;
            *(unsigned short*)(base + 8192 + off) = hl;
        }
        __syncthreads();
        if (tid == 0) {        // producer arrive (post-sync tid0 fence covers all threads' h stores)
            __threadfence();
            unsigned long long my = atomicAdd(&g_bar, 1ULL);
            *tgt_s = (my / NCTA + 1ULL) * NCTA;
        }
        // output store: off the inter-CTA critical path
        out[((size_t)t * BATCH + b) * DHID + dbase + dd] = hval;
    }
}

extern "C" void kernel_launch(void* const* d_in, const int* in_sizes, int n_in,
                              void* d_out, int out_size) {
    const float* batch   = (const float*)d_in[0];
    const int*   lengths = (const int*)  d_in[1];
    const float* c0      = (const float*)d_in[2];
    const float* Wi = (const float*)d_in[3];
    const float* bi = (const float*)d_in[4];
    const float* Wf = (const float*)d_in[5];
    const float* bf = (const float*)d_in[6];
    const float* Wc = (const float*)d_in[7];
    const float* bc = (const float*)d_in[8];
    const float* Wo = (const float*)d_in[9];
    const float* bo = (const float*)d_in[10];
    float* out = (float*)d_out;

    cvt_x_kernel<<<TSTEPS * 16, 128>>>(batch);
    cvt_w_kernel<<<512 + NCTA * NCHL, 256>>>(Wi, Wf, Wc, Wo);

    cudaFuncSetAttribute(gemm_x_kernel, cudaFuncAttributeMaxDynamicSharedMemorySize, SMEM_PRE);
    gemm_x_kernel<<<dim3(32, 128), 256, SMEM_PRE>>>();

    cudaFuncSetAttribute(lstm_mma_kernel, cudaFuncAttributeMaxDynamicSharedMemorySize, SMEM_LOOP);
    lstm_mma_kernel<<<NCTA, NTHR, SMEM_LOOP>>>(lengths, c0, bi, bf, bc, bo, out);
}